// round 16
// baseline (speedup 1.0000x reference)
#include <cuda_runtime.h>
#include <cstdint>

#define BG 4
#define NN 8192
#define EG 65536
#define F0 128
#define F1 256
#define F2 1024
#define NOUTD 18
#define NHEAD 24
#define MTOT (BG*NN)   // 32768 rows total across graphs

// ---------------- scratch (static device globals; ONLY referenced from device code) ----------------
__device__ __align__(16) float    g_dinv[MTOT];
__device__ __align__(16) uint32_t g_agg1[(size_t)MTOT*F0];    // tf32 bits
__device__ __align__(16) float    g_h1  [(size_t)MTOT*F1];
__device__ __align__(16) uint32_t g_agg2[(size_t)MTOT*F1];    // tf32 bits
__device__ __align__(16) uint32_t g_w0t [F0*F1];              // tf32 W0
__device__ __align__(16) uint32_t g_w1t [F1*F2];              // tf32 W1
__device__ __align__(16) float    g_Wc  [F2*NHEAD];
__device__ __align__(16) float    g_bc  [NHEAD];
__device__ __align__(16) float    g_hp  [4*(size_t)MTOT*NHEAD];   // head k-partials (4 N-tiles)
// CSR scratch
__device__ int g_cnt [MTOT];
__device__ int g_cur [MTOT];
__device__ int g_off [MTOT+1];
__device__ int g_bsum[32];
__device__ int g_csrc[BG*EG];

// ---------------- small helpers ----------------
__device__ __forceinline__ uint32_t f2tf32(float x) {
    uint32_t r;
    asm("cvt.rn.tf32.f32 %0, %1;" : "=r"(r) : "f"(x));
    return r;
}
__device__ __forceinline__ void mma_tf32(float c[4], const uint32_t a[4], const uint32_t b[2]) {
    asm("mma.sync.aligned.m16n8k8.row.col.f32.tf32.tf32.f32 "
        "{%0,%1,%2,%3}, {%4,%5,%6,%7}, {%8,%9}, {%0,%1,%2,%3};"
        : "+f"(c[0]), "+f"(c[1]), "+f"(c[2]), "+f"(c[3])
        : "r"(a[0]), "r"(a[1]), "r"(a[2]), "r"(a[3]), "r"(b[0]), "r"(b[1]));
}
__device__ __forceinline__ uint32_t smem_u32(const void* p) {
    uint32_t a;
    asm("{ .reg .u64 t; cvta.to.shared.u64 t, %1; cvt.u32.u64 %0, t; }" : "=r"(a) : "l"(p));
    return a;
}
__device__ __forceinline__ void cp16(uint32_t s, const void* g) {
    asm volatile("cp.async.cg.shared.global [%0], [%1], 16;" :: "r"(s), "l"(g));
}
__device__ __forceinline__ void cp_commit() { asm volatile("cp.async.commit_group;"); }
template<int N> __device__ __forceinline__ void cp_wait() {
    asm volatile("cp.async.wait_group %0;" :: "n"(N));
}

// ---------------- prep: zero cnt, pack Wc/bc, convert W0/W1 to tf32 ----------------
__global__ void prep_k(const float* __restrict__ W0, const float* __restrict__ W1,
                       const float* __restrict__ Wl, const float* __restrict__ bl,
                       const float* __restrict__ Wv, const float* __restrict__ bv) {
    int i = blockIdx.x*blockDim.x + threadIdx.x;       // over F1*F2 = 262144
    g_w1t[i] = f2tf32(W1[i]);
    if (i < F0*F1) g_w0t[i] = f2tf32(W0[i]);
    if (i < MTOT)  g_cnt[i] = 0;
    if (i < F2*NHEAD) {
        int k = i / NHEAD, j = i % NHEAD;
        float v = 0.f;
        if (j < NOUTD)       v = Wl[k*NOUTD + j];
        else if (j == NOUTD) v = Wv[k];
        g_Wc[i] = v;
    }
    if (i < NHEAD) {
        float b = 0.f;
        if (i < NOUTD)       b = bl[i];
        else if (i == NOUTD) b = bv[0];
        g_bc[i] = b;
    }
}

// ---------------- CSR build ----------------
__global__ void cnt_k(const int* __restrict__ edges) {
    int i = blockIdx.x*blockDim.x + threadIdx.x;       // over BG*EG
    int b = i >> 16;
    int e = i & (EG-1);
    int dst = edges[(size_t)b*2*EG + EG + e] & (NN-1);
    atomicAdd(&g_cnt[b*NN + dst], 1);
}

// scan + dinv + cur-zero fused: 32 blocks x 1024 (block-local exclusive scan)
__global__ void __launch_bounds__(1024) scan1_k() {
    __shared__ int warp_s[32];
    int t = threadIdx.x;
    int i = blockIdx.x*1024 + t;
    int v = g_cnt[i];
    g_dinv[i] = rsqrtf(1.0f + (float)v);               // +1 self-loop
    g_cur[i] = 0;
    int x = v;
#pragma unroll
    for (int d = 1; d < 32; d <<= 1) {
        int y = __shfl_up_sync(~0u, x, d);
        if ((t & 31) >= d) x += y;
    }
    if ((t & 31) == 31) warp_s[t >> 5] = x;
    __syncthreads();
    if (t < 32) {
        int y = warp_s[t];
#pragma unroll
        for (int d = 1; d < 32; d <<= 1) {
            int z = __shfl_up_sync(~0u, y, d);
            if (t >= d) y += z;
        }
        warp_s[t] = y;
    }
    __syncthreads();
    int wpre = (t >> 5) ? warp_s[(t >> 5) - 1] : 0;
    int incl = x + wpre;
    g_off[i] = incl - v;                                // block-local exclusive
    if (t == 1023) g_bsum[blockIdx.x] = incl;           // block total
}

// add block prefixes; each block self-sums prior block totals
__global__ void __launch_bounds__(1024) scan3_k() {
    __shared__ int pre;
    int t = threadIdx.x, b = blockIdx.x;
    if (t < 32) {
        int v = (t < b) ? g_bsum[t] : 0;
#pragma unroll
        for (int d = 16; d > 0; d >>= 1) v += __shfl_down_sync(~0u, v, d);
        if (t == 0) pre = v;
    }
    __syncthreads();
    int i = b*1024 + t;
    g_off[i] += pre;
    if (b == 31 && t == 0) g_off[MTOT] = pre + g_bsum[31];
}

__global__ void fill_k(const int* __restrict__ edges) {
    int i = blockIdx.x*blockDim.x + threadIdx.x;       // over BG*EG
    int b = i >> 16;
    int e = i & (EG-1);
    const int* eb = edges + (size_t)b*2*EG;
    int src = eb[e]      & (NN-1);
    int dst = eb[EG + e] & (NN-1);
    int n = b*NN + dst;
    int p = atomicAdd(&g_cur[n], 1);
    g_csrc[g_off[n] + p] = src;
}

// ---------------- gather aggregation (writes tf32): one warp per node ----------------
template<int F>
__device__ __forceinline__ void gather_body(const float* __restrict__ X, uint32_t* __restrict__ agg) {
    int node = blockIdx.x*8 + (threadIdx.x >> 5);      // global node id [0, MTOT)
    int lane = threadIdx.x & 31;
    int bbase = node & ~(NN-1);                        // first node of this graph
    float di = g_dinv[node];
    const float* xr = X + (size_t)node*F;
    float di2 = di*di;

    float4 a0 = *(const float4*)(xr + lane*4);
    a0.x *= di2; a0.y *= di2; a0.z *= di2; a0.w *= di2;
    float4 a1;
    if (F == 256) {
        a1 = *(const float4*)(xr + 128 + lane*4);
        a1.x *= di2; a1.y *= di2; a1.z *= di2; a1.w *= di2;
    }

    int beg = g_off[node], end = g_off[node+1];
    int nxt = (beg < end) ? g_csrc[beg] : 0;           // index prefetch
    for (int j = beg; j < end; j++) {
        int srow = bbase + nxt;
        if (j + 1 < end) nxt = g_csrc[j+1];
        float nrm = g_dinv[srow] * di;
        const float* sr = X + (size_t)srow*F;
        float4 v = *(const float4*)(sr + lane*4);
        a0.x += v.x*nrm; a0.y += v.y*nrm; a0.z += v.z*nrm; a0.w += v.w*nrm;
        if (F == 256) {
            float4 w = *(const float4*)(sr + 128 + lane*4);
            a1.x += w.x*nrm; a1.y += w.y*nrm; a1.z += w.z*nrm; a1.w += w.w*nrm;
        }
    }
    uint32_t* ar = agg + (size_t)node*F;
    uint4 u0 = { f2tf32(a0.x), f2tf32(a0.y), f2tf32(a0.z), f2tf32(a0.w) };
    *(uint4*)(ar + lane*4) = u0;
    if (F == 256) {
        uint4 u1 = { f2tf32(a1.x), f2tf32(a1.y), f2tf32(a1.z), f2tf32(a1.w) };
        *(uint4*)(ar + 128 + lane*4) = u1;
    }
}

__global__ void gather1_k(const float* __restrict__ nodes) { gather_body<F0>(nodes, g_agg1); }
__global__ void gather2_k()                                { gather_body<F1>(g_h1,  g_agg2); }

// ---------------- tf32 GEMM, 3-stage cp.async, CTA tile 128x256x16 ----------------
// 8 warps 2(M)x4(N), warp tile 64x64. FUSE=0: C=relu(A@B+bias). FUSE=1: head partial -> g_hp.
// Pool: A stages 3x[128][20]w = 30720B at 0; B stages 3x[16][264]w = 50688B at 30720 (tot 81408).
// FUSE epilogue reuse: Csp [64][268]f (68608B) at 0; Wcs [256][24]f (24576B) at 68608. Pool 93184B.
#define SMEM_GEMM 93184

template<int N, int K, int FUSE>
__device__ __forceinline__ void mma_gemm_body(const uint32_t* __restrict__ A,
                                              const uint32_t* __restrict__ Bm,
                                              const float* __restrict__ bias,
                                              float* __restrict__ C) {
    extern __shared__ __align__(16) char pool[];
    uint32_t* Aw = (uint32_t*)pool;                  // stage s -> +s*2560 words
    uint32_t* Bw = (uint32_t*)(pool + 30720);        // stage s -> +s*4224 words
    float*    Csp = (float*)pool;                    // [64][268]
    float*    Wcs = (float*)(pool + 68608);          // [256][24]
    const uint32_t sA = smem_u32(pool);
    const uint32_t sB = sA + 30720;

    const int tid  = threadIdx.x;
    const int warp = tid >> 5, lane = tid & 31;
    const int wm = warp & 1, wn = warp >> 1;         // 2(M) x 4(N)
    const int gid = lane >> 2, tig = lane & 3;
    const int bM = blockIdx.y * 128;
    const int bN = blockIdx.x * 256;

    // copy slots: A 512 cp16 (2/thread), B 1024 cp16 (4/thread)
    const int arow0 = tid >> 2,       ac0 = (tid & 3)*4;
    const int arow1 = (tid+256) >> 2, ac1 = ((tid+256) & 3)*4;

    float acc[4][8][4];
#pragma unroll
    for (int i = 0; i < 4; i++)
#pragma unroll
        for (int j = 0; j < 8; j++)
#pragma unroll
            for (int q = 0; q < 4; q++) acc[i][j][q] = 0.f;

    auto issue = [&](int s, int kb) {
        uint32_t a_s = sA + s*10240, b_s = sB + s*16896;
        cp16(a_s + arow0*80 + ac0*4, A + (size_t)(bM+arow0)*K + kb + ac0);
        cp16(a_s + arow1*80 + ac1*4, A + (size_t)(bM+arow1)*K + kb + ac1);
#pragma unroll
        for (int j = 0; j < 4; j++) {
            int slot = tid + j*256;
            int kr = slot >> 6, c4 = (slot & 63)*4;
            cp16(b_s + kr*1056 + c4*4, Bm + (size_t)(kb+kr)*N + bN + c4);
        }
        cp_commit();
    };

    constexpr int NIT = K/16;
    issue(0, 0);
    issue(1, 16);

    for (int it = 0; it < NIT; it++) {
        const int cur = it % 3;
        if (it == NIT-1) cp_wait<0>(); else cp_wait<1>();
        __syncthreads();
        const uint32_t* Ac = Aw + cur*2560;
        const uint32_t* Bc = Bw + cur*4224;
#pragma unroll
        for (int k8 = 0; k8 < 2; k8++) {
            const int kc = k8*8 + tig;
            uint32_t a[4][4], b[8][2];
#pragma unroll
            for (int mj = 0; mj < 4; mj++) {
                int r = wm*64 + mj*16 + gid;
                a[mj][0] = Ac[r*20 + kc];
                a[mj][1] = Ac[(r+8)*20 + kc];
                a[mj][2] = Ac[r*20 + kc+4];
                a[mj][3] = Ac[(r+8)*20 + kc+4];
            }
#pragma unroll
            for (int nj = 0; nj < 8; nj++) {
                int cN = wn*64 + nj*8 + gid;
                b[nj][0] = Bc[kc*264 + cN];
                b[nj][1] = Bc[(kc+4)*264 + cN];
            }
#pragma unroll
            for (int mj = 0; mj < 4; mj++)
#pragma unroll
                for (int nj = 0; nj < 8; nj++)
                    mma_tf32(acc[mj][nj], a[mj], b[nj]);
        }
        if (it + 2 < NIT) issue((it+2) % 3, (it+2)*16);
    }

    if (FUSE == 0) {
#pragma unroll
        for (int mj = 0; mj < 4; mj++) {
            int row0 = bM + wm*64 + mj*16 + gid;
#pragma unroll
            for (int nj = 0; nj < 8; nj++) {
                int col = bN + wn*64 + nj*8 + 2*tig;
                float bx = bias[col], by = bias[col+1];
                float2 v0 = { fmaxf(acc[mj][nj][0] + bx, 0.f), fmaxf(acc[mj][nj][1] + by, 0.f) };
                float2 v1 = { fmaxf(acc[mj][nj][2] + bx, 0.f), fmaxf(acc[mj][nj][3] + by, 0.f) };
                *(float2*)(C + (size_t)row0*N + col)     = v0;
                *(float2*)(C + (size_t)(row0+8)*N + col) = v1;
            }
        }
    } else {
        __syncthreads();   // all MMA smem reads done before pool reuse
        for (int i = tid; i < 256*NHEAD/4; i += 256) {
            int kr = i / 6, c4 = (i % 6)*4;
            *(float4*)(&Wcs[kr*NHEAD + c4]) = *(const float4*)(g_Wc + (size_t)(bN+kr)*NHEAD + c4);
        }
        float* hp = g_hp + (size_t)blockIdx.x*MTOT*NHEAD;
#pragma unroll
        for (int ph = 0; ph < 2; ph++) {
            __syncthreads();
            if (wm == ph) {
#pragma unroll
                for (int mj = 0; mj < 4; mj++) {
                    int r = mj*16 + gid;
#pragma unroll
                    for (int nj = 0; nj < 8; nj++) {
                        int col = wn*64 + nj*8 + 2*tig;
                        float bx = bias[bN+col], by = bias[bN+col+1];
                        Csp[r*268 + col]       = fmaxf(acc[mj][nj][0] + bx, 0.f);
                        Csp[r*268 + col+1]     = fmaxf(acc[mj][nj][1] + by, 0.f);
                        Csp[(r+8)*268 + col]   = fmaxf(acc[mj][nj][2] + bx, 0.f);
                        Csp[(r+8)*268 + col+1] = fmaxf(acc[mj][nj][3] + by, 0.f);
                    }
                }
            }
            __syncthreads();
            if (warp < 4) {   // warp w: m16 tile of the 64-row band, K=256 cols of Csp
                float acch[3][4];
#pragma unroll
                for (int nj = 0; nj < 3; nj++)
#pragma unroll
                    for (int q = 0; q < 4; q++) acch[nj][q] = 0.f;
#pragma unroll
                for (int k8 = 0; k8 < 32; k8++) {
                    const int kc = k8*8 + tig;
                    int r = warp*16 + gid;
                    float af0 = Csp[r*268 + kc],   af1 = Csp[(r+8)*268 + kc];
                    float af2 = Csp[r*268 + kc+4], af3 = Csp[(r+8)*268 + kc+4];
                    uint32_t ah[4] = { f2tf32(af0), f2tf32(af1), f2tf32(af2), f2tf32(af3) };
                    uint32_t al[4] = { f2tf32(af0 - __uint_as_float(ah[0])),
                                       f2tf32(af1 - __uint_as_float(ah[1])),
                                       f2tf32(af2 - __uint_as_float(ah[2])),
                                       f2tf32(af3 - __uint_as_float(ah[3])) };
#pragma unroll
                    for (int nj = 0; nj < 3; nj++) {
                        int cN = nj*8 + gid;
                        float bf0 = Wcs[kc*NHEAD + cN], bf1 = Wcs[(kc+4)*NHEAD + cN];
                        uint32_t bh[2] = { f2tf32(bf0), f2tf32(bf1) };
                        uint32_t bl[2] = { f2tf32(bf0 - __uint_as_float(bh[0])),
                                           f2tf32(bf1 - __uint_as_float(bh[1])) };
                        mma_tf32(acch[nj], ah, bh);
                        mma_tf32(acch[nj], al, bh);
                        mma_tf32(acch[nj], ah, bl);
                    }
                }
                int row0 = bM + ph*64 + warp*16 + gid;
#pragma unroll
                for (int nj = 0; nj < 3; nj++) {
                    int col = nj*8 + 2*tig;
                    *(float2*)(hp + (size_t)row0*NHEAD + col)     = make_float2(acch[nj][0], acch[nj][1]);
                    *(float2*)(hp + (size_t)(row0+8)*NHEAD + col) = make_float2(acch[nj][2], acch[nj][3]);
                }
            }
        }
    }
}

__global__ void __launch_bounds__(256) gemm1_k(const float* __restrict__ b0) {
    mma_gemm_body<F1, F0, 0>(g_agg1, g_w0t, b0, g_h1);
}
__global__ void __launch_bounds__(256) gemm2_k(const float* __restrict__ b1) {
    mma_gemm_body<F2, F1, 1>(g_agg2, g_w1t, b1, nullptr);
}

// ---------------- reduce head partials: out = sum_nb hp[nb] + bc ----------------
__global__ void reduce_k(float* __restrict__ logits, float* __restrict__ values) {
    int idx = blockIdx.x*blockDim.x + threadIdx.x;     // over MTOT*NHEAD
    int row = idx / NHEAD, j = idx % NHEAD;
    float s = g_bc[j];
#pragma unroll
    for (int nb = 0; nb < 4; nb++)
        s += g_hp[(size_t)nb*MTOT*NHEAD + idx];
    if (j < NOUTD)       logits[(size_t)row*NOUTD + j] = s;
    else if (j == NOUTD) values[row] = s;
}

// ---------------- launch ----------------
extern "C" void kernel_launch(void* const* d_in, const int* in_sizes, int n_in,
                              void* d_out, int out_size) {
    int iNodes, iEdges, iW0, ib0, iW1, ib1, iWl, ibl, iWv, ibv;
    if (n_in >= 10 && in_sizes[0] == BG*NN*F0) {          // insertion order
        iNodes=0; iEdges=1; iW0=2; ib0=3; iW1=4; ib1=5; iWl=6; ibl=7; iWv=8; ibv=9;
    } else {                                               // sorted-key order
        iW0=0; iW1=1; iWl=2; iWv=3; ib0=4; ib1=5; ibl=6; ibv=7; iEdges=8; iNodes=9;
    }
    const float* nodes = (const float*)d_in[iNodes];
    const int*   edges = (const int*)  d_in[iEdges];
    const float* W0 = (const float*)d_in[iW0];
    const float* b0 = (const float*)d_in[ib0];
    const float* W1 = (const float*)d_in[iW1];
    const float* b1 = (const float*)d_in[ib1];
    const float* Wl = (const float*)d_in[iWl];
    const float* bl = (const float*)d_in[ibl];
    const float* Wv = (const float*)d_in[iWv];
    const float* bv = (const float*)d_in[ibv];
    float* outp   = (float*)d_out;
    float* logits = outp;
    float* values = outp + (size_t)MTOT*NOUTD;

    static_assert(SMEM_GEMM <= 227*1024, "smem");
    cudaFuncSetAttribute(gemm1_k, cudaFuncAttributeMaxDynamicSharedMemorySize, SMEM_GEMM);
    cudaFuncSetAttribute(gemm2_k, cudaFuncAttributeMaxDynamicSharedMemorySize, SMEM_GEMM);

    // prep (cnt zero + Wc/bc pack + W0/W1 tf32 convert) and CSR build
    prep_k <<<F1*F2/256, 256>>>(W0, W1, Wl, bl, Wv, bv);
    cnt_k  <<<BG*EG/256, 256>>>(edges);
    scan1_k<<<32, 1024>>>();
    scan3_k<<<32, 1024>>>();
    fill_k <<<BG*EG/256, 256>>>(edges);

    // layer 1: gather-aggregate X (128-d, tf32 out) then pipelined tf32 GEMM -> relu
    gather1_k<<<MTOT/8, 256>>>(nodes);
    gemm1_k  <<<dim3(F1/256, MTOT/128), 256, SMEM_GEMM>>>(b0);

    // layer 2: gather-aggregate h1 (256-d, tf32 out) then pipelined GEMM + fused head
    gather2_k<<<MTOT/8, 256>>>();
    gemm2_k  <<<dim3(F2/256, MTOT/128), 256, SMEM_GEMM>>>(b1);

    // reduce head partials -> logits/values
    reduce_k<<<MTOT*NHEAD/256, 256>>>(logits, values);
}

// round 17
// speedup vs baseline: 1.0950x; 1.0950x over previous
#include <cuda_runtime.h>
#include <cstdint>

#define BG 4
#define NN 8192
#define EG 65536
#define F0 128
#define F1 256
#define F2 1024
#define NOUTD 18
#define NHEAD 24
#define MTOT (BG*NN)   // 32768 rows total across graphs

// ---------------- scratch (static device globals; ONLY referenced from device code) ----------------
__device__ __align__(16) float    g_dinv[MTOT];
__device__ __align__(16) uint32_t g_agg1[(size_t)MTOT*F0];    // tf32 bits
__device__ __align__(16) float    g_h1  [(size_t)MTOT*F1];
__device__ __align__(16) uint32_t g_agg2[(size_t)MTOT*F1];    // tf32 bits
__device__ __align__(16) uint32_t g_w0t [F0*F1];              // tf32 W0
__device__ __align__(16) uint32_t g_w1t [F1*F2];              // tf32 W1
__device__ __align__(16) float    g_Wc  [F2*NHEAD];
__device__ __align__(16) float    g_bc  [NHEAD];
__device__ __align__(16) float    g_hp  [8*(size_t)MTOT*NHEAD];   // head k-partials (8 N-tiles)
// CSR scratch
__device__ int g_cnt [MTOT];
__device__ int g_cur [MTOT];
__device__ int g_off [MTOT+1];
__device__ int g_bsum[32];
__device__ int g_csrc[BG*EG];

// ---------------- small helpers ----------------
__device__ __forceinline__ uint32_t f2tf32(float x) {
    uint32_t r;
    asm("cvt.rn.tf32.f32 %0, %1;" : "=r"(r) : "f"(x));
    return r;
}
__device__ __forceinline__ void mma_tf32(float c[4], const uint32_t a[4], const uint32_t b[2]) {
    asm("mma.sync.aligned.m16n8k8.row.col.f32.tf32.tf32.f32 "
        "{%0,%1,%2,%3}, {%4,%5,%6,%7}, {%8,%9}, {%0,%1,%2,%3};"
        : "+f"(c[0]), "+f"(c[1]), "+f"(c[2]), "+f"(c[3])
        : "r"(a[0]), "r"(a[1]), "r"(a[2]), "r"(a[3]), "r"(b[0]), "r"(b[1]));
}
__device__ __forceinline__ uint32_t smem_u32(const void* p) {
    uint32_t a;
    asm("{ .reg .u64 t; cvta.to.shared.u64 t, %1; cvt.u32.u64 %0, t; }" : "=r"(a) : "l"(p));
    return a;
}
__device__ __forceinline__ void cp16(uint32_t s, const void* g) {
    asm volatile("cp.async.cg.shared.global [%0], [%1], 16;" :: "r"(s), "l"(g));
}
__device__ __forceinline__ void cp_commit() { asm volatile("cp.async.commit_group;"); }
template<int N> __device__ __forceinline__ void cp_wait() {
    asm volatile("cp.async.wait_group %0;" :: "n"(N));
}

// ---------------- prep: zero cnt, pack Wc/bc, convert W0/W1 to tf32 ----------------
__global__ void prep_k(const float* __restrict__ W0, const float* __restrict__ W1,
                       const float* __restrict__ Wl, const float* __restrict__ bl,
                       const float* __restrict__ Wv, const float* __restrict__ bv) {
    int i = blockIdx.x*blockDim.x + threadIdx.x;       // over F1*F2 = 262144
    g_w1t[i] = f2tf32(W1[i]);
    if (i < F0*F1) g_w0t[i] = f2tf32(W0[i]);
    if (i < MTOT)  g_cnt[i] = 0;
    if (i < F2*NHEAD) {
        int k = i / NHEAD, j = i % NHEAD;
        float v = 0.f;
        if (j < NOUTD)       v = Wl[k*NOUTD + j];
        else if (j == NOUTD) v = Wv[k];
        g_Wc[i] = v;
    }
    if (i < NHEAD) {
        float b = 0.f;
        if (i < NOUTD)       b = bl[i];
        else if (i == NOUTD) b = bv[0];
        g_bc[i] = b;
    }
}

// ---------------- CSR build ----------------
__global__ void cnt_k(const int* __restrict__ edges) {
    int i = blockIdx.x*blockDim.x + threadIdx.x;       // over BG*EG
    int b = i >> 16;
    int e = i & (EG-1);
    int dst = edges[(size_t)b*2*EG + EG + e] & (NN-1);
    atomicAdd(&g_cnt[b*NN + dst], 1);
}

// scan + dinv + cur-zero fused: 32 blocks x 1024 (block-local exclusive scan)
__global__ void __launch_bounds__(1024) scan1_k() {
    __shared__ int warp_s[32];
    int t = threadIdx.x;
    int i = blockIdx.x*1024 + t;
    int v = g_cnt[i];
    g_dinv[i] = rsqrtf(1.0f + (float)v);               // +1 self-loop
    g_cur[i] = 0;
    int x = v;
#pragma unroll
    for (int d = 1; d < 32; d <<= 1) {
        int y = __shfl_up_sync(~0u, x, d);
        if ((t & 31) >= d) x += y;
    }
    if ((t & 31) == 31) warp_s[t >> 5] = x;
    __syncthreads();
    if (t < 32) {
        int y = warp_s[t];
#pragma unroll
        for (int d = 1; d < 32; d <<= 1) {
            int z = __shfl_up_sync(~0u, y, d);
            if (t >= d) y += z;
        }
        warp_s[t] = y;
    }
    __syncthreads();
    int wpre = (t >> 5) ? warp_s[(t >> 5) - 1] : 0;
    int incl = x + wpre;
    g_off[i] = incl - v;                                // block-local exclusive
    if (t == 1023) g_bsum[blockIdx.x] = incl;           // block total
}

// add block prefixes; each block self-sums prior block totals
__global__ void __launch_bounds__(1024) scan3_k() {
    __shared__ int pre;
    int t = threadIdx.x, b = blockIdx.x;
    if (t < 32) {
        int v = (t < b) ? g_bsum[t] : 0;
#pragma unroll
        for (int d = 16; d > 0; d >>= 1) v += __shfl_down_sync(~0u, v, d);
        if (t == 0) pre = v;
    }
    __syncthreads();
    int i = b*1024 + t;
    g_off[i] += pre;
    if (b == 31 && t == 0) g_off[MTOT] = pre + g_bsum[31];
}

__global__ void fill_k(const int* __restrict__ edges) {
    int i = blockIdx.x*blockDim.x + threadIdx.x;       // over BG*EG
    int b = i >> 16;
    int e = i & (EG-1);
    const int* eb = edges + (size_t)b*2*EG;
    int src = eb[e]      & (NN-1);
    int dst = eb[EG + e] & (NN-1);
    int n = b*NN + dst;
    int p = atomicAdd(&g_cur[n], 1);
    g_csrc[g_off[n] + p] = src;
}

// ---------------- gather aggregation (writes tf32): one warp per node ----------------
template<int F>
__device__ __forceinline__ void gather_body(const float* __restrict__ X, uint32_t* __restrict__ agg) {
    int node = blockIdx.x*8 + (threadIdx.x >> 5);      // global node id [0, MTOT)
    int lane = threadIdx.x & 31;
    int bbase = node & ~(NN-1);                        // first node of this graph
    float di = g_dinv[node];
    const float* xr = X + (size_t)node*F;
    float di2 = di*di;

    float4 a0 = *(const float4*)(xr + lane*4);
    a0.x *= di2; a0.y *= di2; a0.z *= di2; a0.w *= di2;
    float4 a1;
    if (F == 256) {
        a1 = *(const float4*)(xr + 128 + lane*4);
        a1.x *= di2; a1.y *= di2; a1.z *= di2; a1.w *= di2;
    }

    int beg = g_off[node], end = g_off[node+1];
    int nxt = (beg < end) ? g_csrc[beg] : 0;           // index prefetch
    for (int j = beg; j < end; j++) {
        int srow = bbase + nxt;
        if (j + 1 < end) nxt = g_csrc[j+1];
        float nrm = g_dinv[srow] * di;
        const float* sr = X + (size_t)srow*F;
        float4 v = *(const float4*)(sr + lane*4);
        a0.x += v.x*nrm; a0.y += v.y*nrm; a0.z += v.z*nrm; a0.w += v.w*nrm;
        if (F == 256) {
            float4 w = *(const float4*)(sr + 128 + lane*4);
            a1.x += w.x*nrm; a1.y += w.y*nrm; a1.z += w.z*nrm; a1.w += w.w*nrm;
        }
    }
    uint32_t* ar = agg + (size_t)node*F;
    uint4 u0 = { f2tf32(a0.x), f2tf32(a0.y), f2tf32(a0.z), f2tf32(a0.w) };
    *(uint4*)(ar + lane*4) = u0;
    if (F == 256) {
        uint4 u1 = { f2tf32(a1.x), f2tf32(a1.y), f2tf32(a1.z), f2tf32(a1.w) };
        *(uint4*)(ar + 128 + lane*4) = u1;
    }
}

__global__ void gather1_k(const float* __restrict__ nodes) { gather_body<F0>(nodes, g_agg1); }
__global__ void gather2_k()                                { gather_body<F1>(g_h1,  g_agg2); }

// ---------------- tf32 GEMM, 4-stage cp.async pipeline, CTA tile 128x128x16 ----------------
// 8 warps 2(M)x4(N), warp tile 64x32. FUSE=0: C=relu(A@B+bias). FUSE=1: head partial -> g_hp.
// Pool: A stages 4x[128][20]w = 40960B at 0; B stages 4x[16][136]w = 34816B at 40960. Tot 75776B.
// FUSE epilogue reuse: Csp [64][132]f (33792B) at 0; Wcs [128][24]f (12288B) at 33792.
#define SMEM_GEMM 75776

template<int N, int K, int FUSE>
__device__ __forceinline__ void mma_gemm_body(const uint32_t* __restrict__ A,
                                              const uint32_t* __restrict__ Bm,
                                              const float* __restrict__ bias,
                                              float* __restrict__ C) {
    extern __shared__ __align__(16) char pool[];
    uint32_t* Aw = (uint32_t*)pool;                  // stage s -> +s*2560 words
    uint32_t* Bw = (uint32_t*)(pool + 40960);        // stage s -> +s*2176 words
    float*    Csp = (float*)pool;
    float*    Wcs = (float*)(pool + 33792);
    const uint32_t sA = smem_u32(pool);
    const uint32_t sB = sA + 40960;

    const int tid  = threadIdx.x;
    const int warp = tid >> 5, lane = tid & 31;
    const int wm = warp & 1, wn = warp >> 1;
    const int gid = lane >> 2, tig = lane & 3;
    const int bM = blockIdx.y * 128;
    const int bN = blockIdx.x * 128;

    // per-thread copy slots
    const int arow0 = tid >> 2,        ac0 = (tid & 3)*4;
    const int arow1 = (tid+256) >> 2,  ac1 = ((tid+256) & 3)*4;
    const int bkr0  = tid >> 5,        bc0 = (tid & 31)*4;
    const int bkr1  = (tid+256) >> 5,  bc1 = ((tid+256) & 31)*4;

    float acc[4][4][4];
#pragma unroll
    for (int i = 0; i < 4; i++)
#pragma unroll
        for (int j = 0; j < 4; j++)
#pragma unroll
            for (int q = 0; q < 4; q++) acc[i][j][q] = 0.f;

    auto issue = [&](int s, int kb) {
        uint32_t a_s = sA + s*10240, b_s = sB + s*8704;
        cp16(a_s + arow0*80 + ac0*4, A + (size_t)(bM+arow0)*K + kb + ac0);
        cp16(a_s + arow1*80 + ac1*4, A + (size_t)(bM+arow1)*K + kb + ac1);
        cp16(b_s + bkr0*544 + bc0*4, Bm + (size_t)(kb+bkr0)*N + bN + bc0);
        cp16(b_s + bkr1*544 + bc1*4, Bm + (size_t)(kb+bkr1)*N + bN + bc1);
        cp_commit();
    };

    constexpr int NIT = K/16;
    issue(0, 0);
    issue(1, 16);
    issue(2, 32);

    for (int it = 0; it < NIT; it++) {
        const int cur = it & 3;
        if (it < NIT-2)       cp_wait<2>();
        else if (it == NIT-2) cp_wait<1>();
        else                  cp_wait<0>();
        __syncthreads();
        const uint32_t* Ac = Aw + cur*2560;
        const uint32_t* Bc = Bw + cur*2176;
#pragma unroll
        for (int k8 = 0; k8 < 2; k8++) {
            const int kc = k8*8 + tig;
            uint32_t a[4][4], b[4][2];
#pragma unroll
            for (int mj = 0; mj < 4; mj++) {
                int r = wm*64 + mj*16 + gid;
                a[mj][0] = Ac[r*20 + kc];
                a[mj][1] = Ac[(r+8)*20 + kc];
                a[mj][2] = Ac[r*20 + kc+4];
                a[mj][3] = Ac[(r+8)*20 + kc+4];
            }
#pragma unroll
            for (int nj = 0; nj < 4; nj++) {
                int cN = wn*32 + nj*8 + gid;
                b[nj][0] = Bc[kc*136 + cN];
                b[nj][1] = Bc[(kc+4)*136 + cN];
            }
#pragma unroll
            for (int mj = 0; mj < 4; mj++)
#pragma unroll
                for (int nj = 0; nj < 4; nj++)
                    mma_tf32(acc[mj][nj], a[mj], b[nj]);
        }
        if (it + 3 < NIT) issue((it+3) & 3, (it+3)*16);
    }

    if (FUSE == 0) {
#pragma unroll
        for (int mj = 0; mj < 4; mj++) {
            int row0 = bM + wm*64 + mj*16 + gid;
#pragma unroll
            for (int nj = 0; nj < 4; nj++) {
                int col = bN + wn*32 + nj*8 + 2*tig;
                float bx = bias[col], by = bias[col+1];
                float2 v0 = { fmaxf(acc[mj][nj][0] + bx, 0.f), fmaxf(acc[mj][nj][1] + by, 0.f) };
                float2 v1 = { fmaxf(acc[mj][nj][2] + bx, 0.f), fmaxf(acc[mj][nj][3] + by, 0.f) };
                *(float2*)(C + (size_t)row0*N + col)     = v0;
                *(float2*)(C + (size_t)(row0+8)*N + col) = v1;
            }
        }
    } else {
        __syncthreads();   // all MMA smem reads done before pool reuse
        for (int i = tid; i < 128*NHEAD/4; i += 256) {
            int kr = i / 6, c4 = (i % 6)*4;
            *(float4*)(&Wcs[kr*NHEAD + c4]) = *(const float4*)(g_Wc + (size_t)(bN+kr)*NHEAD + c4);
        }
        float* hp = g_hp + (size_t)blockIdx.x*MTOT*NHEAD;
#pragma unroll
        for (int ph = 0; ph < 2; ph++) {
            __syncthreads();
            if (wm == ph) {
#pragma unroll
                for (int mj = 0; mj < 4; mj++) {
                    int r = mj*16 + gid;
#pragma unroll
                    for (int nj = 0; nj < 4; nj++) {
                        int col = wn*32 + nj*8 + 2*tig;
                        float bx = bias[bN+col], by = bias[bN+col+1];
                        Csp[r*132 + col]       = fmaxf(acc[mj][nj][0] + bx, 0.f);
                        Csp[r*132 + col+1]     = fmaxf(acc[mj][nj][1] + by, 0.f);
                        Csp[(r+8)*132 + col]   = fmaxf(acc[mj][nj][2] + bx, 0.f);
                        Csp[(r+8)*132 + col+1] = fmaxf(acc[mj][nj][3] + by, 0.f);
                    }
                }
            }
            __syncthreads();
            if (warp < 4) {
                float acch[3][4];
#pragma unroll
                for (int nj = 0; nj < 3; nj++)
#pragma unroll
                    for (int q = 0; q < 4; q++) acch[nj][q] = 0.f;
#pragma unroll
                for (int k8 = 0; k8 < 16; k8++) {
                    const int kc = k8*8 + tig;
                    int r = warp*16 + gid;
                    float af0 = Csp[r*132 + kc],   af1 = Csp[(r+8)*132 + kc];
                    float af2 = Csp[r*132 + kc+4], af3 = Csp[(r+8)*132 + kc+4];
                    uint32_t ah[4] = { f2tf32(af0), f2tf32(af1), f2tf32(af2), f2tf32(af3) };
                    uint32_t al[4] = { f2tf32(af0 - __uint_as_float(ah[0])),
                                       f2tf32(af1 - __uint_as_float(ah[1])),
                                       f2tf32(af2 - __uint_as_float(ah[2])),
                                       f2tf32(af3 - __uint_as_float(ah[3])) };
#pragma unroll
                    for (int nj = 0; nj < 3; nj++) {
                        int cN = nj*8 + gid;
                        float bf0 = Wcs[kc*NHEAD + cN], bf1 = Wcs[(kc+4)*NHEAD + cN];
                        uint32_t bh[2] = { f2tf32(bf0), f2tf32(bf1) };
                        uint32_t bl[2] = { f2tf32(bf0 - __uint_as_float(bh[0])),
                                           f2tf32(bf1 - __uint_as_float(bh[1])) };
                        mma_tf32(acch[nj], ah, bh);
                        mma_tf32(acch[nj], al, bh);
                        mma_tf32(acch[nj], ah, bl);
                    }
                }
                int row0 = bM + ph*64 + warp*16 + gid;
#pragma unroll
                for (int nj = 0; nj < 3; nj++) {
                    int col = nj*8 + 2*tig;
                    *(float2*)(hp + (size_t)row0*NHEAD + col)     = make_float2(acch[nj][0], acch[nj][1]);
                    *(float2*)(hp + (size_t)(row0+8)*NHEAD + col) = make_float2(acch[nj][2], acch[nj][3]);
                }
            }
        }
    }
}

__global__ void __launch_bounds__(256) gemm1_k(const float* __restrict__ b0) {
    mma_gemm_body<F1, F0, 0>(g_agg1, g_w0t, b0, g_h1);
}
__global__ void __launch_bounds__(256) gemm2_k(const float* __restrict__ b1) {
    mma_gemm_body<F2, F1, 1>(g_agg2, g_w1t, b1, nullptr);
}

// ---------------- reduce head partials: out = sum_nb hp[nb] + bc ----------------
__global__ void reduce_k(float* __restrict__ logits, float* __restrict__ values) {
    int idx = blockIdx.x*blockDim.x + threadIdx.x;     // over MTOT*NHEAD
    int row = idx / NHEAD, j = idx % NHEAD;
    float s = g_bc[j];
#pragma unroll
    for (int nb = 0; nb < 8; nb++)
        s += g_hp[(size_t)nb*MTOT*NHEAD + idx];
    if (j < NOUTD)       logits[(size_t)row*NOUTD + j] = s;
    else if (j == NOUTD) values[row] = s;
}

// ---------------- launch ----------------
extern "C" void kernel_launch(void* const* d_in, const int* in_sizes, int n_in,
                              void* d_out, int out_size) {
    int iNodes, iEdges, iW0, ib0, iW1, ib1, iWl, ibl, iWv, ibv;
    if (n_in >= 10 && in_sizes[0] == BG*NN*F0) {          // insertion order
        iNodes=0; iEdges=1; iW0=2; ib0=3; iW1=4; ib1=5; iWl=6; ibl=7; iWv=8; ibv=9;
    } else {                                               // sorted-key order
        iW0=0; iW1=1; iWl=2; iWv=3; ib0=4; ib1=5; ibl=6; ibv=7; iEdges=8; iNodes=9;
    }
    const float* nodes = (const float*)d_in[iNodes];
    const int*   edges = (const int*)  d_in[iEdges];
    const float* W0 = (const float*)d_in[iW0];
    const float* b0 = (const float*)d_in[ib0];
    const float* W1 = (const float*)d_in[iW1];
    const float* b1 = (const float*)d_in[ib1];
    const float* Wl = (const float*)d_in[iWl];
    const float* bl = (const float*)d_in[ibl];
    const float* Wv = (const float*)d_in[iWv];
    const float* bv = (const float*)d_in[ibv];
    float* outp   = (float*)d_out;
    float* logits = outp;
    float* values = outp + (size_t)MTOT*NOUTD;

    static_assert(SMEM_GEMM <= 227*1024, "smem");
    cudaFuncSetAttribute(gemm1_k, cudaFuncAttributeMaxDynamicSharedMemorySize, SMEM_GEMM);
    cudaFuncSetAttribute(gemm2_k, cudaFuncAttributeMaxDynamicSharedMemorySize, SMEM_GEMM);

    // prep (cnt zero + Wc/bc pack + W0/W1 tf32 convert) and CSR build
    prep_k <<<F1*F2/256, 256>>>(W0, W1, Wl, bl, Wv, bv);
    cnt_k  <<<BG*EG/256, 256>>>(edges);
    scan1_k<<<32, 1024>>>();
    scan3_k<<<32, 1024>>>();
    fill_k <<<BG*EG/256, 256>>>(edges);

    // layer 1: gather-aggregate X (128-d, tf32 out) then pipelined tf32 GEMM -> relu
    gather1_k<<<MTOT/8, 256>>>(nodes);
    gemm1_k  <<<dim3(F1/128, MTOT/128), 256, SMEM_GEMM>>>(b0);

    // layer 2: gather-aggregate h1 (256-d, tf32 out) then pipelined GEMM + fused head
    gather2_k<<<MTOT/8, 256>>>();
    gemm2_k  <<<dim3(F2/128, MTOT/128), 256, SMEM_GEMM>>>(b1);

    // reduce head partials -> logits/values
    reduce_k<<<MTOT*NHEAD/256, 256>>>(logits, values);
}